// round 14
// baseline (speedup 1.0000x reference)
#include <cuda_runtime.h>

#define NQ 12
#define BT 64    // main kernel: 64 threads (2 warps), 1 batch element/thread

typedef unsigned long long ull;

__device__ __forceinline__ float2 cmulc(float2 a, float2 b) {
    return make_float2(a.x * b.x - a.y * b.y, a.x * b.y + a.y * b.x);
}
__device__ __forceinline__ float2 caddc(float2 a, float2 b) {
    return make_float2(a.x + b.x, a.y + b.y);
}

// Batch-independent transfer-matrix tensors:
// bulk  (p=1..11): g_K[(p-1)*32 + s*16 + sg*4 + sgp]
// bound (p=0)    : g_K[352 + j*8 + s*4 + sgp]
__device__ float2 g_K[368];

// ====================== BUILD K (1 CTA, once) ================================
__global__ __launch_bounds__(128)
void build_k_kernel(const float* __restrict__ params)
{
    __shared__ float2 sU[3][12][4];   // fused gates [layer][wire][r*2+s]
    const int tid = threadIdx.x;

    if (tid < 36) {
        const float* p = params + tid * 3;
        float sa, ca; sincosf(0.5f * p[0], &sa, &ca);
        float sb, cb; sincosf(0.5f * p[1], &sb, &cb);
        float sc, cc; sincosf(0.5f * p[2], &sc, &cc);
        float2 m00 = make_float2( cb * ca, -sb * sa);
        float2 m01 = make_float2(-cb * sa, -sb * ca);
        float2 m10 = make_float2( cb * sa, -sb * ca);
        float2 m11 = make_float2( cb * ca,  sb * sa);
        float2 e0 = make_float2(cc, -sc);
        float2 e1 = make_float2(cc,  sc);
        int layer = tid / 12, wire = tid % 12;
        sU[layer][wire][0] = cmulc(e0, m00);
        sU[layer][wire][1] = cmulc(e0, m01);
        sU[layer][wire][2] = cmulc(e1, m10);
        sU[layer][wire][3] = cmulc(e1, m11);
    }
    __syncthreads();

    for (int e = tid; e < 368; e += 128) {
        if (e < 352) {
            int p   = e / 32 + 1;          // 1..11
            int w   = 11 - p;              // wire for bit p
            int rem = e % 32;
            int s   = rem >> 4;
            int sg  = (rem >> 2) & 3;      // sigma  = a + 2b
            int sgp = rem & 3;             // sigma' = a' + 2b'
            int a = sg & 1,  bq = sg >> 1;
            int ap = sgp & 1, bp = sgp >> 1;
            g_K[e] = cmulc(cmulc(sU[2][w][a],
                                 sU[1][w][((a ^ ap) << 1) | bq]),
                           sU[0][w][((bq ^ bp) << 1) | s]);
        } else {
            int r   = e - 352;
            int j   = r >> 3;
            int s   = (r >> 2) & 1;
            int sgp = r & 3;
            int ap = sgp & 1, bp = sgp >> 1;
            float2 acc = make_float2(0.0f, 0.0f);
#pragma unroll
            for (int sg = 0; sg < 4; ++sg) {      // sum over free sigma_0
                int a = sg & 1, bq = sg >> 1;
                acc = caddc(acc,
                    cmulc(cmulc(sU[2][11][(j << 1) | a],
                                sU[1][11][((a ^ ap) << 1) | bq]),
                          sU[0][11][((bq ^ bp) << 1) | s]));
            }
            g_K[e] = acc;
        }
    }
}

// ====================== MAIN: per-batch MPS chain ============================
__global__ __launch_bounds__(BT)
void qnn_mps_kernel(const float* __restrict__ x,
                    float* __restrict__ out, int B)
{
    __shared__ float2 sK[368];      // [0..351] bulk, [352..367] boundary
    __shared__ float  sX[BT * NQ];

    const int tid = threadIdx.x;

    // Stage x: BT*12 floats = BT*3 float4, coalesced, guarded.
    {
        const float4* x4 = (const float4*)(x) + blockIdx.x * (BT * NQ / 4);
        float4* s4 = (float4*)sX;
        int total4 = (B * NQ) / 4 - blockIdx.x * (BT * NQ / 4);
#pragma unroll
        for (int i = 0; i < 3; ++i) {
            int e = i * BT + tid;
            s4[e] = (e < total4) ? x4[e] : make_float4(0.f, 0.f, 0.f, 0.f);
        }
    }
    // Stage K: 368 float2 = 184 float4, L2-hot broadcast loads.
    {
        const float4* k4 = (const float4*)g_K;
        float4* s4 = (float4*)sK;
#pragma unroll
        for (int i = 0; i < 3; ++i) {
            int e = i * BT + tid;
            if (e < 184) s4[e] = k4[e];
        }
    }
    __syncthreads();

    const int b = blockIdx.x * BT + tid;

    float fc[NQ], fs[NQ];
#pragma unroll
    for (int w = 0; w < NQ; ++w) {
        float s, c; __sincosf(0.5f * sX[tid * NQ + w], &s, &c);
        fc[w] = c; fs[w] = s;
    }

    // p = 11 (wire 0): sigma_12 = 0 boundary -> column 0 of K_11
    float2 wv[4];
#pragma unroll
    for (int sg = 0; sg < 4; ++sg) {
        float2 k0 = sK[10 * 32 + 0 * 16 + sg * 4 + 0];
        float2 k1 = sK[10 * 32 + 1 * 16 + sg * 4 + 0];
        wv[sg] = make_float2(fc[0] * k0.x + fs[0] * k1.x,
                             fc[0] * k0.y + fs[0] * k1.y);
    }

    // p = 10..1 (wire 11-p): w <- (c*K0 + s*K1) w
#pragma unroll
    for (int p = 10; p >= 1; --p) {
        float c = fc[11 - p], s = fs[11 - p];
        const float2* kb = &sK[(p - 1) * 32];
        float2 nw[4];
#pragma unroll
        for (int sg = 0; sg < 4; ++sg) {
            float2 a0 = make_float2(0.0f, 0.0f);
            float2 a1 = make_float2(0.0f, 0.0f);
#pragma unroll
            for (int sp = 0; sp < 4; ++sp) {
                a0 = caddc(a0, cmulc(kb[sg * 4 + sp], wv[sp]));
                a1 = caddc(a1, cmulc(kb[16 + sg * 4 + sp], wv[sp]));
            }
            nw[sg] = make_float2(c * a0.x + s * a1.x,
                                 c * a0.y + s * a1.y);
        }
#pragma unroll
        for (int sg = 0; sg < 4; ++sg) wv[sg] = nw[sg];
    }

    // p = 0 (wire 11): boundary row-sums, two j variants
    float pr[2];
#pragma unroll
    for (int j = 0; j < 2; ++j) {
        const float2* ka = &sK[352 + j * 8];
        float2 a0 = make_float2(0.0f, 0.0f);
        float2 a1 = make_float2(0.0f, 0.0f);
#pragma unroll
        for (int sp = 0; sp < 4; ++sp) {
            a0 = caddc(a0, cmulc(ka[sp], wv[sp]));
            a1 = caddc(a1, cmulc(ka[4 + sp], wv[sp]));
        }
        float re = fc[11] * a0.x + fs[11] * a1.x;
        float im = fc[11] * a0.y + fs[11] * a1.y;
        pr[j] = re * re + im * im;
    }

    if (b < B) {
        float inv = 1.0f / (pr[0] + pr[1]);
        ((float2*)out)[b] = make_float2(pr[0] * inv, pr[1] * inv);
    }
}

extern "C" void kernel_launch(void* const* d_in, const int* in_sizes, int n_in,
                              void* d_out, int out_size) {
    const float* x      = (const float*)d_in[0];  // (B, 12) float32
    const float* params = (const float*)d_in[1];  // (3, 12, 3) float32
    float* out = (float*)d_out;                   // (B, 2) float32
    int B = in_sizes[0] / NQ;

    build_k_kernel<<<1, 128>>>(params);
    qnn_mps_kernel<<<(B + BT - 1) / BT, BT>>>(x, out, B);
}

// round 15
// speedup vs baseline: 1.2788x; 1.2788x over previous
#include <cuda_runtime.h>

#define NQ 12
#define BT 128   // 4 warps: warps 0,2 = LEFT, warps 1,3 = RIGHT; 64 elems/CTA

__device__ __forceinline__ float2 cmulc(float2 a, float2 b) {
    return make_float2(a.x * b.x - a.y * b.y, a.x * b.y + a.y * b.x);
}
__device__ __forceinline__ float2 caddc(float2 a, float2 b) {
    return make_float2(a.x + b.x, a.y + b.y);
}

// Single kernel: bond-4 MPS transfer-matrix chain, contracted from BOTH ends.
// amp_j = L_j . T1 T2 ... T10 . R   (validated decomposition, R12/R14)
//   RIGHT warps: v = T4..T10 . R        (7 matvecs)
//   LEFT  warps: u_j = L_j . T1 T2 T3   (2 rows x 3 steps), then amp_j = u_j.v
__global__ __launch_bounds__(BT)
void qnn_mps_kernel(const float* __restrict__ x,
                    const float* __restrict__ params,
                    float* __restrict__ out, int B)
{
    __shared__ float2 sU[3][12][4];   // fused gates [layer][wire][r*2+s]
    __shared__ float2 sK[368];        // bulk [0..351], boundary [352..367]
    __shared__ float  sX[64 * NQ];    // staged x rows (64 elements)
    __shared__ float2 sV[64][4];      // right-half results per element

    const int tid  = threadIdx.x;
    const int lane = tid & 31;
    const int wid  = tid >> 5;
    const int le   = (wid >> 1) * 32 + lane;       // local element 0..63
    const int e    = blockIdx.x * 64 + le;         // global batch element

    // ---- stage x: 64*12 floats = 192 float4, coalesced, guarded ------------
    {
        const float4* x4 = (const float4*)(x) + blockIdx.x * 192;
        float4* s4 = (float4*)sX;
        int total4 = (B * NQ) / 4 - blockIdx.x * 192;
#pragma unroll
        for (int i = 0; i < 2; ++i) {
            int e4 = i * BT + tid;
            if (e4 < 192)
                s4[e4] = (e4 < total4) ? x4[e4] : make_float4(0.f, 0.f, 0.f, 0.f);
        }
    }

    // ---- fused gates U = RZ RX RY (validated) -------------------------------
    if (tid < 36) {
        const float* p = params + tid * 3;
        float sa, ca; sincosf(0.5f * p[0], &sa, &ca);
        float sb, cb; sincosf(0.5f * p[1], &sb, &cb);
        float sc, cc; sincosf(0.5f * p[2], &sc, &cc);
        float2 m00 = make_float2( cb * ca, -sb * sa);
        float2 m01 = make_float2(-cb * sa, -sb * ca);
        float2 m10 = make_float2( cb * sa, -sb * ca);
        float2 m11 = make_float2( cb * ca,  sb * sa);
        float2 e0 = make_float2(cc, -sc);
        float2 e1 = make_float2(cc,  sc);
        int layer = tid / 12, wire = tid % 12;
        sU[layer][wire][0] = cmulc(e0, m00);
        sU[layer][wire][1] = cmulc(e0, m01);
        sU[layer][wire][2] = cmulc(e1, m10);
        sU[layer][wire][3] = cmulc(e1, m11);
    }
    __syncthreads();

    // ---- K tensors (validated indexing, R12/R14) ----------------------------
    for (int i = tid; i < 368; i += BT) {
        if (i < 352) {
            int p   = i / 32 + 1;          // 1..11
            int w   = 11 - p;
            int rem = i % 32;
            int s   = rem >> 4;
            int sg  = (rem >> 2) & 3;      // sigma  = a + 2b
            int sgp = rem & 3;             // sigma' = a' + 2b'
            int a = sg & 1,  bq = sg >> 1;
            int ap = sgp & 1, bp = sgp >> 1;
            sK[i] = cmulc(cmulc(sU[2][w][a],
                                sU[1][w][((a ^ ap) << 1) | bq]),
                          sU[0][w][((bq ^ bp) << 1) | s]);
        } else {
            int r   = i - 352;
            int j   = r >> 3;
            int s   = (r >> 2) & 1;
            int sgp = r & 3;
            int ap = sgp & 1, bp = sgp >> 1;
            float2 acc = make_float2(0.0f, 0.0f);
#pragma unroll
            for (int sg = 0; sg < 4; ++sg) {
                int a = sg & 1, bq = sg >> 1;
                acc = caddc(acc,
                    cmulc(cmulc(sU[2][11][(j << 1) | a],
                                sU[1][11][((a ^ ap) << 1) | bq]),
                          sU[0][11][((bq ^ bp) << 1) | s]));
            }
            sK[i] = acc;
        }
    }
    __syncthreads();

    const float* xr = &sX[le * NQ];
    float2 u0[4], u1[4];            // LEFT state (lives across the sync)

    if (wid & 1) {
        // ================= RIGHT: v = T4..T10 . R ============================
        float fcw[8], fsw[8];                      // wires 0..7
#pragma unroll
        for (int w = 0; w < 8; ++w)
            __sincosf(0.5f * xr[w], &fsw[w], &fcw[w]);

        // p = 11 init (wire 0): column 0 of K_11
        float2 wv[4];
#pragma unroll
        for (int sg = 0; sg < 4; ++sg) {
            float2 k0 = sK[10 * 32 + sg * 4];
            float2 k1 = sK[10 * 32 + 16 + sg * 4];
            wv[sg] = make_float2(fcw[0] * k0.x + fsw[0] * k1.x,
                                 fcw[0] * k0.y + fsw[0] * k1.y);
        }
        // p = 10..4 (wire 11-p = 1..7)
#pragma unroll
        for (int p = 10; p >= 4; --p) {
            float c = fcw[11 - p], s = fsw[11 - p];
            const float2* kb = &sK[(p - 1) * 32];
            float2 nw[4];
#pragma unroll
            for (int sg = 0; sg < 4; ++sg) {
                float2 a0 = make_float2(0.0f, 0.0f);
                float2 a1 = make_float2(0.0f, 0.0f);
#pragma unroll
                for (int sp = 0; sp < 4; ++sp) {
                    a0 = caddc(a0, cmulc(kb[sg * 4 + sp], wv[sp]));
                    a1 = caddc(a1, cmulc(kb[16 + sg * 4 + sp], wv[sp]));
                }
                nw[sg] = make_float2(c * a0.x + s * a1.x,
                                     c * a0.y + s * a1.y);
            }
#pragma unroll
            for (int sg = 0; sg < 4; ++sg) wv[sg] = nw[sg];
        }
#pragma unroll
        for (int sg = 0; sg < 4; ++sg) sV[le][sg] = wv[sg];
    } else {
        // ================= LEFT: u_j = L_j . T1 T2 T3 ========================
        float fcw[4], fsw[4];                      // wires 8..11 -> idx w-8
#pragma unroll
        for (int w = 0; w < 4; ++w)
            __sincosf(0.5f * xr[8 + w], &fsw[w], &fcw[w]);

        float c11 = fcw[3], s11 = fsw[3];          // wire 11 (p=0 boundary)
#pragma unroll
        for (int sp = 0; sp < 4; ++sp) {
            float2 k00 = sK[352 + sp],     k01 = sK[352 + 4 + sp];
            float2 k10 = sK[352 + 8 + sp], k11 = sK[352 + 12 + sp];
            u0[sp] = make_float2(c11 * k00.x + s11 * k01.x,
                                 c11 * k00.y + s11 * k01.y);
            u1[sp] = make_float2(c11 * k10.x + s11 * k11.x,
                                 c11 * k10.y + s11 * k11.y);
        }
        // p = 1..3 (wire 11-p = 10, 9, 8 -> fcw[2], fcw[1], fcw[0])
#pragma unroll
        for (int p = 1; p <= 3; ++p) {
            float c = fcw[11 - p - 8], s = fsw[11 - p - 8];
            const float2* kb = &sK[(p - 1) * 32];
            float2 n0[4], n1[4];
#pragma unroll
            for (int sgp = 0; sgp < 4; ++sgp) {
                float2 a00 = make_float2(0.f, 0.f), a01 = make_float2(0.f, 0.f);
                float2 a10 = make_float2(0.f, 0.f), a11 = make_float2(0.f, 0.f);
#pragma unroll
                for (int sg = 0; sg < 4; ++sg) {
                    float2 k0 = kb[sg * 4 + sgp];
                    float2 k1 = kb[16 + sg * 4 + sgp];
                    a00 = caddc(a00, cmulc(u0[sg], k0));
                    a01 = caddc(a01, cmulc(u0[sg], k1));
                    a10 = caddc(a10, cmulc(u1[sg], k0));
                    a11 = caddc(a11, cmulc(u1[sg], k1));
                }
                n0[sgp] = make_float2(c * a00.x + s * a01.x,
                                      c * a00.y + s * a01.y);
                n1[sgp] = make_float2(c * a10.x + s * a11.x,
                                      c * a10.y + s * a11.y);
            }
#pragma unroll
            for (int sgp = 0; sgp < 4; ++sgp) { u0[sgp] = n0[sgp]; u1[sgp] = n1[sgp]; }
        }
    }
    __syncthreads();

    // ---- LEFT warps combine and emit ----------------------------------------
    if (!(wid & 1)) {
        float2 amp0 = make_float2(0.f, 0.f), amp1 = make_float2(0.f, 0.f);
#pragma unroll
        for (int sp = 0; sp < 4; ++sp) {
            float2 v = sV[le][sp];
            amp0 = caddc(amp0, cmulc(u0[sp], v));
            amp1 = caddc(amp1, cmulc(u1[sp], v));
        }
        float p0 = amp0.x * amp0.x + amp0.y * amp0.y;
        float p1 = amp1.x * amp1.x + amp1.y * amp1.y;
        if (e < B) {
            float inv = 1.0f / (p0 + p1);
            ((float2*)out)[e] = make_float2(p0 * inv, p1 * inv);
        }
    }
}

extern "C" void kernel_launch(void* const* d_in, const int* in_sizes, int n_in,
                              void* d_out, int out_size) {
    const float* x      = (const float*)d_in[0];  // (B, 12) float32
    const float* params = (const float*)d_in[1];  // (3, 12, 3) float32
    float* out = (float*)d_out;                   // (B, 2) float32
    int B = in_sizes[0] / NQ;

    qnn_mps_kernel<<<(B + 63) / 64, BT>>>(x, params, out, B);
}

// round 16
// speedup vs baseline: 1.5853x; 1.2396x over previous
#include <cuda_runtime.h>

#define NQ 12
#define BT 128   // 4 warps; 4 lanes per element -> 32 elements per CTA

__device__ __forceinline__ float2 cmulc(float2 a, float2 b) {
    return make_float2(a.x * b.x - a.y * b.y, a.x * b.y + a.y * b.x);
}
__device__ __forceinline__ float2 caddc(float2 a, float2 b) {
    return make_float2(a.x + b.x, a.y + b.y);
}

// Single kernel: bond-4 MPS transfer-matrix chain, 4 lanes per batch element
// (lane l owns bond component sg = l; cross-component data via warp shuffles).
// amp_j = L_j . T1 .. T10 . R  -- decomposition and K indexing validated
// through R12/R14/R15.
__global__ __launch_bounds__(BT)
void qnn_mps_kernel(const float* __restrict__ x,
                    const float* __restrict__ params,
                    float* __restrict__ out, int B)
{
    __shared__ float2 sU[3][12][4];   // fused gates [layer][wire][r*2+s]
    __shared__ float2 sK[368];        // bulk [0..351], boundary [352..367]
    __shared__ float  sX[32 * NQ];    // staged x rows (32 elements per CTA)

    const int tid  = threadIdx.x;
    const int lane = tid & 31;
    const int wid  = tid >> 5;
    const int l    = lane & 3;                 // bond component this lane owns
    const int gbase = lane & ~3;               // first lane of this element's group
    const int le   = wid * 8 + (lane >> 2);    // local element 0..31
    const int e    = blockIdx.x * 32 + le;     // global batch element

    // ---- stage x: 32*12 floats = 96 float4, coalesced, guarded -------------
    if (tid < 96) {
        const float4* x4 = (const float4*)(x) + blockIdx.x * 96;
        int total4 = (B * NQ) / 4 - blockIdx.x * 96;
        ((float4*)sX)[tid] = (tid < total4) ? x4[tid]
                                            : make_float4(0.f, 0.f, 0.f, 0.f);
    }

    // ---- fused gates U = RZ RX RY (validated) -------------------------------
    if (tid < 36) {
        const float* p = params + tid * 3;
        float sa, ca; sincosf(0.5f * p[0], &sa, &ca);
        float sb, cb; sincosf(0.5f * p[1], &sb, &cb);
        float sc, cc; sincosf(0.5f * p[2], &sc, &cc);
        float2 m00 = make_float2( cb * ca, -sb * sa);
        float2 m01 = make_float2(-cb * sa, -sb * ca);
        float2 m10 = make_float2( cb * sa, -sb * ca);
        float2 m11 = make_float2( cb * ca,  sb * sa);
        float2 e0 = make_float2(cc, -sc);
        float2 e1 = make_float2(cc,  sc);
        int layer = tid / 12, wire = tid % 12;
        sU[layer][wire][0] = cmulc(e0, m00);
        sU[layer][wire][1] = cmulc(e0, m01);
        sU[layer][wire][2] = cmulc(e1, m10);
        sU[layer][wire][3] = cmulc(e1, m11);
    }
    __syncthreads();

    // ---- K tensors (validated indexing) -------------------------------------
    for (int i = tid; i < 368; i += BT) {
        if (i < 352) {
            int p   = i / 32 + 1;          // 1..11
            int w   = 11 - p;
            int rem = i % 32;
            int s   = rem >> 4;
            int sg  = (rem >> 2) & 3;      // sigma  = a + 2b
            int sgp = rem & 3;             // sigma' = a' + 2b'
            int a = sg & 1,  bq = sg >> 1;
            int ap = sgp & 1, bp = sgp >> 1;
            sK[i] = cmulc(cmulc(sU[2][w][a],
                                sU[1][w][((a ^ ap) << 1) | bq]),
                          sU[0][w][((bq ^ bp) << 1) | s]);
        } else {
            int r   = i - 352;
            int j   = r >> 3;
            int s   = (r >> 2) & 1;
            int sgp = r & 3;
            int ap = sgp & 1, bp = sgp >> 1;
            float2 acc = make_float2(0.0f, 0.0f);
#pragma unroll
            for (int sg = 0; sg < 4; ++sg) {
                int a = sg & 1, bq = sg >> 1;
                acc = caddc(acc,
                    cmulc(cmulc(sU[2][11][(j << 1) | a],
                                sU[1][11][((a ^ ap) << 1) | bq]),
                          sU[0][11][((bq ^ bp) << 1) | s]));
            }
            sK[i] = acc;
        }
    }
    __syncthreads();

    // ---- per-element wire angles (broadcast LDS within the 4-lane group) ----
    const float* xr = &sX[le * NQ];
    float fc[NQ], fs[NQ];
#pragma unroll
    for (int w = 0; w < NQ; ++w)
        __sincosf(0.5f * xr[w], &fs[w], &fc[w]);

    // ---- p = 11 init (wire 0): column 0 of K_11; lane owns sg = l -----------
    float2 wv;
    {
        float2 k0 = sK[10 * 32 + l * 4];          // s = 0
        float2 k1 = sK[10 * 32 + 16 + l * 4];     // s = 1
        wv = make_float2(fc[0] * k0.x + fs[0] * k1.x,
                         fc[0] * k0.y + fs[0] * k1.y);
    }

    // ---- p = 10..1 (wire 11-p): wv_l <- sum_sp (c*K0 + s*K1)[l][sp] wv_sp ---
#pragma unroll
    for (int p = 10; p >= 1; --p) {
        float c = fc[11 - p], s = fs[11 - p];
        const float2* kb = &sK[(p - 1) * 32];
        float2 acc = make_float2(0.0f, 0.0f);
#pragma unroll
        for (int sp = 0; sp < 4; ++sp) {
            float wx = __shfl_sync(0xffffffffu, wv.x, gbase | sp);
            float wy = __shfl_sync(0xffffffffu, wv.y, gbase | sp);
            float2 k0 = kb[l * 4 + sp];
            float2 k1 = kb[16 + l * 4 + sp];
            float2 m = make_float2(c * k0.x + s * k1.x,
                                   c * k0.y + s * k1.y);
            acc = caddc(acc, cmulc(m, make_float2(wx, wy)));
        }
        wv = acc;
    }

    // ---- p = 0 boundary: per-lane term + 4-lane butterfly reduction ---------
    float c11 = fc[11], s11 = fs[11];
    float pr[2];
#pragma unroll
    for (int j = 0; j < 2; ++j) {
        const float2* ka = &sK[352 + j * 8];
        float2 k0 = ka[l], k1 = ka[4 + l];
        float2 m = make_float2(c11 * k0.x + s11 * k1.x,
                               c11 * k0.y + s11 * k1.y);
        float2 t = cmulc(m, wv);
        t.x += __shfl_xor_sync(0xffffffffu, t.x, 1);
        t.y += __shfl_xor_sync(0xffffffffu, t.y, 1);
        t.x += __shfl_xor_sync(0xffffffffu, t.x, 2);
        t.y += __shfl_xor_sync(0xffffffffu, t.y, 2);
        pr[j] = t.x * t.x + t.y * t.y;
    }

    if (l == 0 && e < B) {
        float inv = 1.0f / (pr[0] + pr[1]);
        ((float2*)out)[e] = make_float2(pr[0] * inv, pr[1] * inv);
    }
}

extern "C" void kernel_launch(void* const* d_in, const int* in_sizes, int n_in,
                              void* d_out, int out_size) {
    const float* x      = (const float*)d_in[0];  // (B, 12) float32
    const float* params = (const float*)d_in[1];  // (3, 12, 3) float32
    float* out = (float*)d_out;                   // (B, 2) float32
    int B = in_sizes[0] / NQ;

    qnn_mps_kernel<<<(B + 31) / 32, BT>>>(x, params, out, B);
}